// round 8
// baseline (speedup 1.0000x reference)
#include <cuda_runtime.h>
#include <cuda_bf16.h>
#include <cstdint>

// ---------------- problem dims (fixed) ----------------
#define BATCH   32
#define RDIM    5
#define NNODES  1024
#define DDIM    256
#define HDIM    256
#define NG      6                   // w_0 + 5 relations
#define MTOT    (BATCH * NNODES)    // 32768

// ---------------- tiling ----------------
#define TM      128                 // CTA M tile
#define TH      64                  // CTA H tile
#define SA      264                 // padded A row stride (bf16 elems), 528 B
#define SAB     (SA * 2)            // A row stride bytes
#define ASZ     (TM * SAB)          // 67584 B per A buffer

// B chunk: 64 rows x 128 cols bf16, padded row stride 272 B (conflict-free)
#define BROW    272
#define BCHUNK  (TH * BROW)         // 17408 B per (hi|lo) chunk
#define BSTAGE  (2 * BCHUNK)        // 34816 B per stage (hi + lo)
#define NCHUNK  (NG * 2)            // 12 chunks (g x k-half)

#define SM_AHI  0
#define SM_ALO  (ASZ)
#define SM_B0   (2 * ASZ)                  // 135168
#define SM_TOTAL (SM_B0 + 2 * BSTAGE)      // 204800 B

#define NTHREADS 512                // 16 warps: 8 per K-group

// ---------------- device scratch ----------------
__device__ __align__(16) __nv_bfloat16 g_nhi[MTOT * DDIM];       // nodes hi [m][d]
__device__ __align__(16) __nv_bfloat16 g_nlo[MTOT * DDIM];       // nodes lo
__device__ __align__(16) __nv_bfloat16 g_whi[NG * HDIM * DDIM];  // [g][h][d] hi
__device__ __align__(16) __nv_bfloat16 g_wlo[NG * HDIM * DDIM];  // [g][h][d] lo
__device__ float g_invc[BATCH * RDIM * NNODES];                  // 1/rowsum (0 -> 1)

// ---------------- helpers ----------------
__device__ __forceinline__ uint32_t smem_u32(const void* p) {
    uint32_t a;
    asm("{ .reg .u64 t; cvta.to.shared.u64 t, %1; cvt.u32.u64 %0, t; }" : "=r"(a) : "l"(p));
    return a;
}
__device__ __forceinline__ void ldm4(uint32_t* r, uint32_t addr) {
    asm volatile("ldmatrix.sync.aligned.m8n8.x4.shared.b16 {%0,%1,%2,%3}, [%4];"
                 : "=r"(r[0]), "=r"(r[1]), "=r"(r[2]), "=r"(r[3]) : "r"(addr));
}
__device__ __forceinline__ void mma16816(float* c, const uint32_t* a,
                                         uint32_t b0, uint32_t b1) {
    asm volatile("mma.sync.aligned.m16n8k16.row.col.f32.bf16.bf16.f32 "
                 "{%0,%1,%2,%3}, {%4,%5,%6,%7}, {%8,%9}, {%0,%1,%2,%3};"
                 : "+f"(c[0]), "+f"(c[1]), "+f"(c[2]), "+f"(c[3])
                 : "r"(a[0]), "r"(a[1]), "r"(a[2]), "r"(a[3]), "r"(b0), "r"(b1));
}
__device__ __forceinline__ void cpasync16(uint32_t dst, const void* src) {
    asm volatile("cp.async.cg.shared.global [%0], [%1], 16;" :: "r"(dst), "l"(src));
}
template<int N> __device__ __forceinline__ void cpwait() {
    asm volatile("cp.async.wait_group %0;" :: "n"(N));
}
#define CP_COMMIT() asm volatile("cp.async.commit_group;" ::: "memory")

// ---------------- kernel 1: adj row sums -> reciprocal ----------------
__global__ void row_sum_kernel(const float* __restrict__ adj) {
    int gwarp = (blockIdx.x * blockDim.x + threadIdx.x) >> 5;
    int lane  = threadIdx.x & 31;
    if (gwarp >= BATCH * RDIM * NNODES) return;
    const float4* row = reinterpret_cast<const float4*>(adj) + (size_t)gwarp * 256;
    float s = 0.0f;
    #pragma unroll
    for (int i = 0; i < 8; i++) {
        float4 v = row[lane + i * 32];
        s += (v.x + v.y) + (v.z + v.w);
    }
    #pragma unroll
    for (int o = 16; o > 0; o >>= 1) s += __shfl_xor_sync(0xffffffffu, s, o);
    if (lane == 0) {
        if (s == 0.0f) s = 1.0f;
        g_invc[gwarp] = 1.0f / s;
    }
}

// ---------------- kernel 2: nodes -> bf16 hi/lo ----------------
__global__ void prep_nodes_kernel(const float* __restrict__ nodes) {
    int idx = blockIdx.x * blockDim.x + threadIdx.x;    // float4 index
    if (idx >= MTOT * DDIM / 4) return;
    float4 v = reinterpret_cast<const float4*>(nodes)[idx];
    __nv_bfloat16 h0 = __float2bfloat16(v.x), h1 = __float2bfloat16(v.y);
    __nv_bfloat16 h2 = __float2bfloat16(v.z), h3 = __float2bfloat16(v.w);
    __nv_bfloat16 l0 = __float2bfloat16(v.x - __bfloat162float(h0));
    __nv_bfloat16 l1 = __float2bfloat16(v.y - __bfloat162float(h1));
    __nv_bfloat16 l2 = __float2bfloat16(v.z - __bfloat162float(h2));
    __nv_bfloat16 l3 = __float2bfloat16(v.w - __bfloat162float(h3));
    __nv_bfloat162 hA = {h0, h1}, hB = {h2, h3}, lA = {l0, l1}, lB = {l2, l3};
    uint2 hp = make_uint2(*reinterpret_cast<uint32_t*>(&hA), *reinterpret_cast<uint32_t*>(&hB));
    uint2 lp = make_uint2(*reinterpret_cast<uint32_t*>(&lA), *reinterpret_cast<uint32_t*>(&lB));
    reinterpret_cast<uint2*>(g_nhi)[idx] = hp;
    reinterpret_cast<uint2*>(g_nlo)[idx] = lp;
}

// ---------------- kernel 3: weights -> stacked [g][h][d] bf16 hi/lo -------
__global__ void prep_w_kernel(const float* __restrict__ w0,
                              const float* __restrict__ wr) {
    int idx = blockIdx.x * blockDim.x + threadIdx.x;
    if (idx >= NG * HDIM * DDIM) return;
    int g = idx / (HDIM * DDIM);
    int r = idx % (HDIM * DDIM);      // = h*DDIM + d
    float v = (g == 0) ? w0[r] : wr[(g - 1) * HDIM * DDIM + r];
    __nv_bfloat16 h = __float2bfloat16(v);
    g_whi[idx] = h;
    g_wlo[idx] = __float2bfloat16(v - __bfloat162float(h));
}

// ---------------- kernel 4: mma.sync split-bf16 fused multi-GEMM ---------
// grid (MTOT/TM, HDIM/TH), 512 threads (16 warps).
// In-CTA split-K: warps 0-7 do kc 0-3 of each chunk, warps 8-15 do kc 4-7.
// B staged as 12 (g, k-half) chunks, double-buffered via cp.async.
// per g: acc = Ahi.Bhi^T + Ahi.Blo^T + Alo.Bhi^T; run += s(g,m)*acc.
// Final: group 1's run reduced into group 0 via smem, group 0 writes out.
__global__ __launch_bounds__(NTHREADS, 1) void gemm_mma_kernel(float* __restrict__ out) {
    extern __shared__ char smem[];
    const uint32_t sb = smem_u32(smem);
    const int tid  = threadIdx.x;
    const int lane = tid & 31;
    const int wid8 = (tid >> 5) & 7;    // warp within group
    const int grp  = tid >> 8;          // 0: kc 0-3, 1: kc 4-7
    const int wm = wid8 >> 1;           // 0..3
    const int wh = wid8 & 1;            // 0..1
    const int tile_m = blockIdx.x * TM;
    const int tile_h = blockIdx.y * TH;

    // ---- async-stage A hi/lo: [TM x 256] bf16, padded rows (group 0) ----
    #pragma unroll
    for (int i = tid; i < TM * 32; i += NTHREADS) {
        int row = i >> 5;
        int cq  = i & 31;                       // 8-elem chunk
        size_t src = (size_t)(tile_m + row) * DDIM + cq * 8;
        uint32_t d = sb + (uint32_t)row * SAB + cq * 16;
        cpasync16(d + SM_AHI, &g_nhi[src]);
        cpasync16(d + SM_ALO, &g_nlo[src]);
    }
    CP_COMMIT();

    // ---- chunk prefetch helper (B tile k-half, hi+lo) ----
    auto stage_chunk = [&](int stage, int c) {
        int g = c >> 1, kh = c & 1;
        uint32_t base = sb + SM_B0 + (uint32_t)stage * BSTAGE;
        #pragma unroll
        for (int i = tid; i < TH * 16; i += NTHREADS) {
            int row = i >> 4;
            int cq  = i & 15;
            size_t src = ((size_t)g * HDIM + tile_h + row) * DDIM + kh * 128 + cq * 8;
            uint32_t d = base + (uint32_t)row * BROW + cq * 16;
            cpasync16(d, &g_whi[src]);
            cpasync16(d + BCHUNK, &g_wlo[src]);
        }
        CP_COMMIT();
    };

    stage_chunk(0, 0);      // group 1

    // ---- per-thread ldmatrix base offsets ----
    // A (row-major m x k): lanes 0-15 rows, lanes 16-31 same rows k+8
    const uint32_t aRow = (uint32_t)(wm * 32 + (lane & 15)) * SAB + (lane >> 4) * 16;
    const uint32_t aHi0 = sb + SM_AHI + aRow;
    const uint32_t aHi1 = aHi0 + 16 * SAB;
    const uint32_t aLo0 = sb + SM_ALO + aRow;
    const uint32_t aLo1 = aLo0 + 16 * SAB;
    // B (row-major n x k): r0:(n0-7,k0-7) r1:(n0-7,k8-15) r2:(n8-15,k0-7) r3:(n8-15,k8-15)
    const int n_loc  = (lane & 7) + ((lane >> 4) << 3);
    const int k_half = (lane >> 3) & 1;
    const uint32_t bOff = (uint32_t)(wh * 32 + n_loc) * BROW + (uint32_t)k_half * 16;

    // ---- per-row scales (4 rows per thread: +0,+8,+16,+24) ----
    const int r0 = tile_m + wm * 32 + (lane >> 2);
    float sc[NG][4];
    #pragma unroll
    for (int j = 0; j < 4; j++) sc[0][j] = 1.0f;
    #pragma unroll
    for (int g = 1; g < NG; g++)
        #pragma unroll
        for (int j = 0; j < 4; j++) {
            int row = r0 + j * 8;
            int b = row >> 10, n = row & 1023;
            sc[g][j] = g_invc[((size_t)b * RDIM + (g - 1)) * NNODES + n];
        }

    float run[2][4][4];
    #pragma unroll
    for (int mi = 0; mi < 2; mi++)
        #pragma unroll
        for (int ni = 0; ni < 4; ni++)
            #pragma unroll
            for (int c = 0; c < 4; c++) run[mi][ni][c] = 0.0f;

    float acc[2][4][4];

    #pragma unroll 1
    for (int c = 0; c < NCHUNK; c++) {
        // prefetch next chunk into the other stage (its consumers finished at
        // the end of iteration c-1, enforced by the trailing __syncthreads)
        if (c + 1 < NCHUNK) {
            stage_chunk((c + 1) & 1, c + 1);
            cpwait<1>();        // chunk c (and A) arrived; c+1 in flight
        } else {
            cpwait<0>();
        }
        __syncthreads();

        const int kh = c & 1;
        if (kh == 0) {
            #pragma unroll
            for (int mi = 0; mi < 2; mi++)
                #pragma unroll
                for (int ni = 0; ni < 4; ni++)
                    #pragma unroll
                    for (int q = 0; q < 4; q++) acc[mi][ni][q] = 0.0f;
        }

        const uint32_t stb = sb + SM_B0 + (uint32_t)(c & 1) * BSTAGE + bOff;
        const uint32_t bH0 = stb;
        const uint32_t bH1 = stb + 16 * BROW;
        const uint32_t bL0 = stb + BCHUNK;
        const uint32_t bL1 = stb + BCHUNK + 16 * BROW;
        const uint32_t kaBase = (uint32_t)kh * 8 * 32;

        // this group's quarter of K: kc_eff = grp*4 + kc
        #pragma unroll 2
        for (int kc = 0; kc < 4; kc++) {
            const uint32_t ko = (uint32_t)(grp * 4 + kc) * 32;
            const uint32_t ka = kaBase + ko;
            uint32_t ah0[4], ah1[4], al0[4], al1[4];
            uint32_t bh0[4], bh1[4], bl0[4], bl1[4];
            ldm4(ah0, aHi0 + ka);
            ldm4(ah1, aHi1 + ka);
            ldm4(bh0, bH0 + ko);
            ldm4(bh1, bH1 + ko);
            ldm4(al0, aLo0 + ka);
            ldm4(al1, aLo1 + ka);
            ldm4(bl0, bL0 + ko);
            ldm4(bl1, bL1 + ko);

            // hi * hi
            mma16816(acc[0][0], ah0, bh0[0], bh0[1]);
            mma16816(acc[0][1], ah0, bh0[2], bh0[3]);
            mma16816(acc[0][2], ah0, bh1[0], bh1[1]);
            mma16816(acc[0][3], ah0, bh1[2], bh1[3]);
            mma16816(acc[1][0], ah1, bh0[0], bh0[1]);
            mma16816(acc[1][1], ah1, bh0[2], bh0[3]);
            mma16816(acc[1][2], ah1, bh1[0], bh1[1]);
            mma16816(acc[1][3], ah1, bh1[2], bh1[3]);
            // hi * lo
            mma16816(acc[0][0], ah0, bl0[0], bl0[1]);
            mma16816(acc[0][1], ah0, bl0[2], bl0[3]);
            mma16816(acc[0][2], ah0, bl1[0], bl1[1]);
            mma16816(acc[0][3], ah0, bl1[2], bl1[3]);
            mma16816(acc[1][0], ah1, bl0[0], bl0[1]);
            mma16816(acc[1][1], ah1, bl0[2], bl0[3]);
            mma16816(acc[1][2], ah1, bl1[0], bl1[1]);
            mma16816(acc[1][3], ah1, bl1[2], bl1[3]);
            // lo * hi
            mma16816(acc[0][0], al0, bh0[0], bh0[1]);
            mma16816(acc[0][1], al0, bh0[2], bh0[3]);
            mma16816(acc[0][2], al0, bh1[0], bh1[1]);
            mma16816(acc[0][3], al0, bh1[2], bh1[3]);
            mma16816(acc[1][0], al1, bh0[0], bh0[1]);
            mma16816(acc[1][1], al1, bh0[2], bh0[3]);
            mma16816(acc[1][2], al1, bh1[0], bh1[1]);
            mma16816(acc[1][3], al1, bh1[2], bh1[3]);
        }

        if (kh == 1) {
            const int g = c >> 1;
            #pragma unroll
            for (int mi = 0; mi < 2; mi++)
                #pragma unroll
                for (int ni = 0; ni < 4; ni++) {
                    float s0 = sc[g][mi * 2 + 0];
                    float s1 = sc[g][mi * 2 + 1];
                    run[mi][ni][0] += s0 * acc[mi][ni][0];
                    run[mi][ni][1] += s0 * acc[mi][ni][1];
                    run[mi][ni][2] += s1 * acc[mi][ni][2];
                    run[mi][ni][3] += s1 * acc[mi][ni][3];
                }
        }
        __syncthreads();    // stage (c&1) free for reuse at iteration c+1
    }

    // ---- cross-group reduction: group 1 spills run into dead B region ----
    if (grp == 1) {
        float* red = reinterpret_cast<float*>(smem + SM_B0) + (tid - 256) * 32;
        #pragma unroll
        for (int mi = 0; mi < 2; mi++)
            #pragma unroll
            for (int ni = 0; ni < 4; ni++)
                *reinterpret_cast<float4*>(red + (mi * 4 + ni) * 4) =
                    make_float4(run[mi][ni][0], run[mi][ni][1],
                                run[mi][ni][2], run[mi][ni][3]);
    }
    __syncthreads();
    if (grp == 0) {
        const float* red = reinterpret_cast<const float*>(smem + SM_B0) + tid * 32;
        #pragma unroll
        for (int mi = 0; mi < 2; mi++)
            #pragma unroll
            for (int ni = 0; ni < 4; ni++) {
                float4 v = *reinterpret_cast<const float4*>(red + (mi * 4 + ni) * 4);
                run[mi][ni][0] += v.x;
                run[mi][ni][1] += v.y;
                run[mi][ni][2] += v.z;
                run[mi][ni][3] += v.w;
            }

        // ---- epilogue: write fp32 output ----
        #pragma unroll
        for (int mi = 0; mi < 2; mi++) {
            int rowA = tile_m + wm * 32 + mi * 16 + (lane >> 2);
            #pragma unroll
            for (int ni = 0; ni < 4; ni++) {
                int col = tile_h + wh * 32 + ni * 8 + (lane & 3) * 2;
                *reinterpret_cast<float2*>(&out[(size_t)rowA * HDIM + col]) =
                    make_float2(run[mi][ni][0], run[mi][ni][1]);
                *reinterpret_cast<float2*>(&out[(size_t)(rowA + 8) * HDIM + col]) =
                    make_float2(run[mi][ni][2], run[mi][ni][3]);
            }
        }
    }
}

// ---------------- launch ----------------
extern "C" void kernel_launch(void* const* d_in, const int* in_sizes, int n_in,
                              void* d_out, int out_size) {
    const float* nodes = (const float*)d_in[0];
    const float* adj   = (const float*)d_in[1];
    const float* w0    = (const float*)d_in[2];
    const float* wr    = (const float*)d_in[3];
    float* out = (float*)d_out;

    cudaFuncSetAttribute(gemm_mma_kernel,
                         cudaFuncAttributeMaxDynamicSharedMemorySize, SM_TOTAL);

    {
        int nthreads = BATCH * RDIM * NNODES * 32;
        row_sum_kernel<<<(nthreads + 255) / 256, 256>>>(adj);
    }
    prep_nodes_kernel<<<(MTOT * DDIM / 4 + 255) / 256, 256>>>(nodes);
    prep_w_kernel<<<(NG * HDIM * DDIM + 255) / 256, 256>>>(w0, wr);
    gemm_mma_kernel<<<dim3(MTOT / TM, HDIM / TH), NTHREADS, SM_TOTAL>>>(out);
}

// round 9
// speedup vs baseline: 1.4735x; 1.4735x over previous
#include <cuda_runtime.h>
#include <cuda_fp16.h>
#include <cstdint>

// ---------------- problem dims (fixed) ----------------
#define BATCH   32
#define RDIM    5
#define NNODES  1024
#define DDIM    256
#define HDIM    256
#define NG      6                   // w_0 + 5 relations
#define MTOT    (BATCH * NNODES)    // 32768

// ---------------- tiling ----------------
#define TM      128                 // CTA M tile
#define TH      64                  // CTA H tile
#define SA      264                 // padded A row stride (fp16 elems), 528 B
#define SAB     (SA * 2)            // A row stride bytes
#define ASZ     (TM * SAB)          // 67584 B per A buffer

// g0 chunks: 64 rows x 128 cols fp16, row stride 272 B (hi at 0, lo at +BCHUNK)
#define BROW    272
#define BCHUNK  (TH * BROW)         // 17408
// relation chunks: 64 rows x 256 cols fp16, row stride 528 B
#define BROWR   528
#define BSTAGE  34816               // stage slot (fits both chunk types)
#define NCHUNK  7                   // c0,c1: g0 half-K (3-pass); c2..c6: g1..g5 full-K

#define SM_AHI  0
#define SM_ALO  (ASZ)
#define SM_B0   (2 * ASZ)                  // 135168
#define SM_TOTAL (SM_B0 + 2 * BSTAGE)      // 204800 B

// ---------------- device scratch ----------------
__device__ __align__(16) __half g_nhi[MTOT * DDIM];        // nodes fp16 hi [m][d]
__device__ __align__(16) __half g_nlo[MTOT * DDIM];        // nodes fp16 lo
__device__ __align__(16) __half g_whi[NG * HDIM * DDIM];   // [g][h][d] fp16 hi
__device__ __align__(16) __half g_wlo[HDIM * DDIM];        // w0 fp16 lo (g=0 only)
__device__ float g_invc[BATCH * RDIM * NNODES];            // 1/rowsum (0 -> 1)

// ---------------- helpers ----------------
__device__ __forceinline__ uint32_t smem_u32(const void* p) {
    uint32_t a;
    asm("{ .reg .u64 t; cvta.to.shared.u64 t, %1; cvt.u32.u64 %0, t; }" : "=r"(a) : "l"(p));
    return a;
}
__device__ __forceinline__ void ldm4(uint32_t* r, uint32_t addr) {
    asm volatile("ldmatrix.sync.aligned.m8n8.x4.shared.b16 {%0,%1,%2,%3}, [%4];"
                 : "=r"(r[0]), "=r"(r[1]), "=r"(r[2]), "=r"(r[3]) : "r"(addr));
}
__device__ __forceinline__ void mma16816(float* c, const uint32_t* a,
                                         uint32_t b0, uint32_t b1) {
    asm volatile("mma.sync.aligned.m16n8k16.row.col.f32.f16.f16.f32 "
                 "{%0,%1,%2,%3}, {%4,%5,%6,%7}, {%8,%9}, {%0,%1,%2,%3};"
                 : "+f"(c[0]), "+f"(c[1]), "+f"(c[2]), "+f"(c[3])
                 : "r"(a[0]), "r"(a[1]), "r"(a[2]), "r"(a[3]), "r"(b0), "r"(b1));
}
__device__ __forceinline__ void cpasync16(uint32_t dst, const void* src) {
    asm volatile("cp.async.cg.shared.global [%0], [%1], 16;" :: "r"(dst), "l"(src));
}
template<int N> __device__ __forceinline__ void cpwait() {
    asm volatile("cp.async.wait_group %0;" :: "n"(N));
}
#define CP_COMMIT() asm volatile("cp.async.commit_group;" ::: "memory")

// ---------------- kernel 1: adj row sums -> reciprocal ----------------
__global__ void row_sum_kernel(const float* __restrict__ adj) {
    int gwarp = (blockIdx.x * blockDim.x + threadIdx.x) >> 5;
    int lane  = threadIdx.x & 31;
    if (gwarp >= BATCH * RDIM * NNODES) return;
    const float4* row = reinterpret_cast<const float4*>(adj) + (size_t)gwarp * 256;
    float s = 0.0f;
    #pragma unroll
    for (int i = 0; i < 8; i++) {
        float4 v = row[lane + i * 32];
        s += (v.x + v.y) + (v.z + v.w);
    }
    #pragma unroll
    for (int o = 16; o > 0; o >>= 1) s += __shfl_xor_sync(0xffffffffu, s, o);
    if (lane == 0) {
        if (s == 0.0f) s = 1.0f;
        g_invc[gwarp] = 1.0f / s;
    }
}

// ---------------- kernel 2: nodes -> fp16 hi/lo ----------------
__global__ void prep_nodes_kernel(const float* __restrict__ nodes) {
    int idx = blockIdx.x * blockDim.x + threadIdx.x;    // float4 index
    if (idx >= MTOT * DDIM / 4) return;
    float4 v = reinterpret_cast<const float4*>(nodes)[idx];
    __half h0 = __float2half_rn(v.x), h1 = __float2half_rn(v.y);
    __half h2 = __float2half_rn(v.z), h3 = __float2half_rn(v.w);
    __half l0 = __float2half_rn(v.x - __half2float(h0));
    __half l1 = __float2half_rn(v.y - __half2float(h1));
    __half l2 = __float2half_rn(v.z - __half2float(h2));
    __half l3 = __float2half_rn(v.w - __half2float(h3));
    __half2 hA = {h0, h1}, hB = {h2, h3}, lA = {l0, l1}, lB = {l2, l3};
    uint2 hp = make_uint2(*reinterpret_cast<uint32_t*>(&hA), *reinterpret_cast<uint32_t*>(&hB));
    uint2 lp = make_uint2(*reinterpret_cast<uint32_t*>(&lA), *reinterpret_cast<uint32_t*>(&lB));
    reinterpret_cast<uint2*>(g_nhi)[idx] = hp;
    reinterpret_cast<uint2*>(g_nlo)[idx] = lp;
}

// ---------------- kernel 3: weights -> stacked [g][h][d] fp16 ------------
__global__ void prep_w_kernel(const float* __restrict__ w0,
                              const float* __restrict__ wr) {
    int idx = blockIdx.x * blockDim.x + threadIdx.x;
    if (idx >= NG * HDIM * DDIM) return;
    int g = idx / (HDIM * DDIM);
    int r = idx % (HDIM * DDIM);      // = h*DDIM + d
    float v = (g == 0) ? w0[r] : wr[(g - 1) * HDIM * DDIM + r];
    __half h = __float2half_rn(v);
    g_whi[idx] = h;
    if (g == 0) g_wlo[r] = __float2half_rn(v - __half2float(h));
}

// ---------------- kernel 4: mma.sync fp16 fused multi-GEMM ---------------
// grid (MTOT/TM, HDIM/TH), 256 threads (8 warps, 4x2 over (m,h)).
// c0,c1: w0 half-K chunks, 3-pass hi/lo split (accumulated directly in run).
// c2..c6: relation g=c-1 full-K chunk, 1-pass fp16; run += s(g,m)*acc.
// B chunks double-buffered via cp.async.
__global__ __launch_bounds__(256, 1) void gemm_mma_kernel(float* __restrict__ out) {
    extern __shared__ char smem[];
    const uint32_t sb = smem_u32(smem);
    const int tid  = threadIdx.x;
    const int wid  = tid >> 5;
    const int lane = tid & 31;
    const int wm = wid >> 1;            // 0..3
    const int wh = wid & 1;             // 0..1
    const int tile_m = blockIdx.x * TM;
    const int tile_h = blockIdx.y * TH;

    // ---- async-stage A hi/lo: [TM x 256] fp16, padded rows (group 0) ----
    #pragma unroll
    for (int i = tid; i < TM * 32; i += 256) {
        int row = i >> 5;
        int cq  = i & 31;                       // 8-elem chunk
        size_t src = (size_t)(tile_m + row) * DDIM + cq * 8;
        uint32_t d = sb + (uint32_t)row * SAB + cq * 16;
        cpasync16(d + SM_AHI, &g_nhi[src]);
        cpasync16(d + SM_ALO, &g_nlo[src]);
    }
    CP_COMMIT();

    // ---- chunk prefetch helper ----
    auto stage_chunk = [&](int stage, int c) {
        uint32_t base = sb + SM_B0 + (uint32_t)stage * BSTAGE;
        if (c < 2) {
            // w0 half-K chunk: hi + lo, 64 rows x 128 cols
            #pragma unroll
            for (int i = tid; i < TH * 16; i += 256) {
                int row = i >> 4;
                int cq  = i & 15;
                size_t src = (size_t)(tile_h + row) * DDIM + c * 128 + cq * 8;
                uint32_t d = base + (uint32_t)row * BROW + cq * 16;
                cpasync16(d, &g_whi[src]);
                cpasync16(d + BCHUNK, &g_wlo[src]);
            }
        } else {
            // relation full-K chunk: hi only, 64 rows x 256 cols
            int g = c - 1;
            #pragma unroll
            for (int i = tid; i < TH * 32; i += 256) {
                int row = i >> 5;
                int cq  = i & 31;
                size_t src = ((size_t)g * HDIM + tile_h + row) * DDIM + cq * 8;
                uint32_t d = base + (uint32_t)row * BROWR + cq * 16;
                cpasync16(d, &g_whi[src]);
            }
        }
        CP_COMMIT();
    };

    stage_chunk(0, 0);      // group 1

    // ---- per-thread ldmatrix base offsets ----
    // A (row-major m x k): lanes 0-15 rows, lanes 16-31 same rows k+8
    const uint32_t aRow = (uint32_t)(wm * 32 + (lane & 15)) * SAB + (lane >> 4) * 16;
    const uint32_t aHi0 = sb + SM_AHI + aRow;
    const uint32_t aHi1 = aHi0 + 16 * SAB;
    const uint32_t aLo0 = sb + SM_ALO + aRow;
    const uint32_t aLo1 = aLo0 + 16 * SAB;
    // B (row-major n x k): r0:(n0-7,k0-7) r1:(n0-7,k8-15) r2:(n8-15,k0-7) r3:(n8-15,k8-15)
    const int n_loc  = (lane & 7) + ((lane >> 4) << 3);
    const int k_half = (lane >> 3) & 1;
    const uint32_t bOffH = (uint32_t)(wh * 32 + n_loc) * BROW  + (uint32_t)k_half * 16;
    const uint32_t bOffR = (uint32_t)(wh * 32 + n_loc) * BROWR + (uint32_t)k_half * 16;

    // ---- per-row scales (4 rows per thread: +0,+8,+16,+24), g=1..5 ------
    const int r0 = tile_m + wm * 32 + (lane >> 2);
    float sc[RDIM][4];
    #pragma unroll
    for (int g = 0; g < RDIM; g++)
        #pragma unroll
        for (int j = 0; j < 4; j++) {
            int row = r0 + j * 8;
            int b = row >> 10, n = row & 1023;
            sc[g][j] = g_invc[((size_t)b * RDIM + g) * NNODES + n];
        }

    float run[2][4][4];
    #pragma unroll
    for (int mi = 0; mi < 2; mi++)
        #pragma unroll
        for (int ni = 0; ni < 4; ni++)
            #pragma unroll
            for (int c = 0; c < 4; c++) run[mi][ni][c] = 0.0f;

    #pragma unroll 1
    for (int c = 0; c < NCHUNK; c++) {
        if (c + 1 < NCHUNK) {
            stage_chunk((c + 1) & 1, c + 1);
            cpwait<1>();        // chunk c (and A) arrived; c+1 in flight
        } else {
            cpwait<0>();
        }
        __syncthreads();

        const uint32_t stb = sb + SM_B0 + (uint32_t)(c & 1) * BSTAGE;

        if (c < 2) {
            // ---- w0 half-K chunk: 3-pass split, accumulate into run ----
            const uint32_t kaBase = (uint32_t)c * 256;      // c*8*32
            const uint32_t bH = stb + bOffH;
            const uint32_t bL = stb + BCHUNK + bOffH;
            #pragma unroll 2
            for (int kc = 0; kc < 8; kc++) {
                const uint32_t ko = (uint32_t)kc * 32;
                const uint32_t ka = kaBase + ko;
                uint32_t ah0[4], ah1[4], al0[4], al1[4];
                uint32_t bh0[4], bh1[4], bl0[4], bl1[4];
                ldm4(ah0, aHi0 + ka);
                ldm4(ah1, aHi1 + ka);
                ldm4(bh0, bH + ko);
                ldm4(bh1, bH + 16 * BROW + ko);
                ldm4(al0, aLo0 + ka);
                ldm4(al1, aLo1 + ka);
                ldm4(bl0, bL + ko);
                ldm4(bl1, bL + 16 * BROW + ko);

                // hi * hi
                mma16816(run[0][0], ah0, bh0[0], bh0[1]);
                mma16816(run[0][1], ah0, bh0[2], bh0[3]);
                mma16816(run[0][2], ah0, bh1[0], bh1[1]);
                mma16816(run[0][3], ah0, bh1[2], bh1[3]);
                mma16816(run[1][0], ah1, bh0[0], bh0[1]);
                mma16816(run[1][1], ah1, bh0[2], bh0[3]);
                mma16816(run[1][2], ah1, bh1[0], bh1[1]);
                mma16816(run[1][3], ah1, bh1[2], bh1[3]);
                // hi * lo
                mma16816(run[0][0], ah0, bl0[0], bl0[1]);
                mma16816(run[0][1], ah0, bl0[2], bl0[3]);
                mma16816(run[0][2], ah0, bl1[0], bl1[1]);
                mma16816(run[0][3], ah0, bl1[2], bl1[3]);
                mma16816(run[1][0], ah1, bl0[0], bl0[1]);
                mma16816(run[1][1], ah1, bl0[2], bl0[3]);
                mma16816(run[1][2], ah1, bl1[0], bl1[1]);
                mma16816(run[1][3], ah1, bl1[2], bl1[3]);
                // lo * hi
                mma16816(run[0][0], al0, bh0[0], bh0[1]);
                mma16816(run[0][1], al0, bh0[2], bh0[3]);
                mma16816(run[0][2], al0, bh1[0], bh1[1]);
                mma16816(run[0][3], al0, bh1[2], bh1[3]);
                mma16816(run[1][0], al1, bh0[0], bh0[1]);
                mma16816(run[1][1], al1, bh0[2], bh0[3]);
                mma16816(run[1][2], al1, bh1[0], bh1[1]);
                mma16816(run[1][3], al1, bh1[2], bh1[3]);
            }
        } else {
            // ---- relation full-K chunk: 1-pass fp16 into acc ----
            float acc[2][4][4];
            #pragma unroll
            for (int mi = 0; mi < 2; mi++)
                #pragma unroll
                for (int ni = 0; ni < 4; ni++)
                    #pragma unroll
                    for (int q = 0; q < 4; q++) acc[mi][ni][q] = 0.0f;

            const uint32_t bH = stb + bOffR;
            #pragma unroll 4
            for (int kc = 0; kc < 16; kc++) {
                const uint32_t ko = (uint32_t)kc * 32;
                uint32_t a0[4], a1[4], b0[4], b1[4];
                ldm4(a0, aHi0 + ko);
                ldm4(a1, aHi1 + ko);
                ldm4(b0, bH + ko);
                ldm4(b1, bH + 16 * BROWR + ko);
                mma16816(acc[0][0], a0, b0[0], b0[1]);
                mma16816(acc[0][1], a0, b0[2], b0[3]);
                mma16816(acc[0][2], a0, b1[0], b1[1]);
                mma16816(acc[0][3], a0, b1[2], b1[3]);
                mma16816(acc[1][0], a1, b0[0], b0[1]);
                mma16816(acc[1][1], a1, b0[2], b0[3]);
                mma16816(acc[1][2], a1, b1[0], b1[1]);
                mma16816(acc[1][3], a1, b1[2], b1[3]);
            }

            const int g = c - 2;            // 0..4 -> relation index
            #pragma unroll
            for (int mi = 0; mi < 2; mi++)
                #pragma unroll
                for (int ni = 0; ni < 4; ni++) {
                    float s0 = sc[g][mi * 2 + 0];
                    float s1 = sc[g][mi * 2 + 1];
                    run[mi][ni][0] += s0 * acc[mi][ni][0];
                    run[mi][ni][1] += s0 * acc[mi][ni][1];
                    run[mi][ni][2] += s1 * acc[mi][ni][2];
                    run[mi][ni][3] += s1 * acc[mi][ni][3];
                }
        }
        __syncthreads();    // stage (c&1) free for reuse at iteration c+1
    }

    // ---- epilogue: write fp32 output ----
    #pragma unroll
    for (int mi = 0; mi < 2; mi++) {
        int rowA = tile_m + wm * 32 + mi * 16 + (lane >> 2);
        #pragma unroll
        for (int ni = 0; ni < 4; ni++) {
            int col = tile_h + wh * 32 + ni * 8 + (lane & 3) * 2;
            *reinterpret_cast<float2*>(&out[(size_t)rowA * HDIM + col]) =
                make_float2(run[mi][ni][0], run[mi][ni][1]);
            *reinterpret_cast<float2*>(&out[(size_t)(rowA + 8) * HDIM + col]) =
                make_float2(run[mi][ni][2], run[mi][ni][3]);
        }
    }
}

// ---------------- launch ----------------
extern "C" void kernel_launch(void* const* d_in, const int* in_sizes, int n_in,
                              void* d_out, int out_size) {
    const float* nodes = (const float*)d_in[0];
    const float* adj   = (const float*)d_in[1];
    const float* w0    = (const float*)d_in[2];
    const float* wr    = (const float*)d_in[3];
    float* out = (float*)d_out;

    cudaFuncSetAttribute(gemm_mma_kernel,
                         cudaFuncAttributeMaxDynamicSharedMemorySize, SM_TOTAL);

    {
        int nthreads = BATCH * RDIM * NNODES * 32;
        row_sum_kernel<<<(nthreads + 255) / 256, 256>>>(adj);
    }
    prep_nodes_kernel<<<(MTOT * DDIM / 4 + 255) / 256, 256>>>(nodes);
    prep_w_kernel<<<(NG * HDIM * DDIM + 255) / 256, 256>>>(w0, wr);
    gemm_mma_kernel<<<dim3(MTOT / TM, HDIM / TH), 256, SM_TOTAL>>>(out);
}